// round 14
// baseline (speedup 1.0000x reference)
#include <cuda_runtime.h>
#include <cstdint>

#define BB 8
#define NN 8192
#define MM 2048
#define NUM_ITER 4
#define BASE_ALPHA 0.1f
#define BLOCKS_PER_BATCH 64   // NN/128

// Per-iter per-batch max bits + per-iter per-batch arrival counters.
__device__ int g_maxbits[NUM_ITER * BB];
__device__ int g_arrive [NUM_ITER * BB];

// ---------------------------------------------------------------------------
// f32x2 packed helpers (Blackwell FFMA2 path, PTX fma.rn.f32x2)
// ---------------------------------------------------------------------------
__device__ __forceinline__ uint64_t pack2(float lo, float hi) {
    uint64_t r;
    asm("mov.b64 %0, {%1, %2};" : "=l"(r) : "f"(lo), "f"(hi));
    return r;
}
__device__ __forceinline__ uint64_t ffma2(uint64_t a, uint64_t b, uint64_t c) {
    uint64_t d;
    asm("fma.rn.f32x2 %0, %1, %2, %3;" : "=l"(d) : "l"(a), "l"(b), "l"(c));
    return d;
}
__device__ __forceinline__ void unpack2(uint64_t v, float& lo, float& hi) {
    asm("mov.b64 {%0, %1}, %2;" : "=f"(lo), "=f"(hi) : "l"(v));
}

// ---------------------------------------------------------------------------
// Init: zero the max slots and barrier counters.
// ---------------------------------------------------------------------------
__global__ void ipgr_init_kernel() {
    int i = threadIdx.x;
    if (i < NUM_ITER * BB) {
        g_maxbits[i] = 0;
        g_arrive[i]  = 0;
    }
}

// ---------------------------------------------------------------------------
// Persistent NN + refine kernel: all NUM_ITER iterations in one launch.
// block = 128 threads (4 warps), grid = (NN/128, BB) = 512 blocks. smem 33KB
// + <=128 regs -> >=4 blocks/SM co-resident (592 slots >= 512): the per-batch
// software barrier cannot deadlock.
// Inner loop slot-cost-optimized (FFMA2 costs 3 issue slots via RF banking):
//  - 16-k-step fully-unrolled segments -> LDS immediate offsets, loop
//    arithmetic ~0.7 slots/k-step (was ~4).
//  - 8-m group tournament: 2 quad-mins (3 FMNMX each) + 1 combine FMNMX +
//    one strict-< update per group -> earliest group kept (groups ordered by
//    m within a slice). Position inside the winning 16-candidate group is
//    recovered by bit-exact scalar recomputation (scalar fma.rn == each
//    f32x2 lane), scanning m DESCENDING so the smallest matching m survives
//    -> exact first-index tie-break. Cross-slice/lane merges compare
//    (value, then m).
// Lane layout: q = lane>>3 (one of 4 interleaved M-slices, vector v = 4k+q,
// conflict-free LDS); sub = lane&7; 4 points per thread.
// Comparison key: t = |y|^2/2 - x.y (argmin-equivalent; |x|^2 const/point).
// ---------------------------------------------------------------------------
__global__ void __launch_bounds__(128)
ipgr_persist_kernel(const float* __restrict__ pred,
                    const float* __restrict__ partial,
                    float* __restrict__ out) {
    // SoA tile of partial: yx | yy | yz | yh(=0.5*|y|^2), each MM floats.
    __shared__ __align__(16) float sm[4 * MM];
    __shared__ float smax[4];
    __shared__ float s_mx;

    const int b = blockIdx.y;
    const float* p = partial + (size_t)b * MM * 3;

    for (int m = threadIdx.x; m < MM; m += 128) {
        float yx = p[m * 3 + 0];
        float yy = p[m * 3 + 1];
        float yz = p[m * 3 + 2];
        sm[m]          = yx;
        sm[MM + m]     = yy;
        sm[2 * MM + m] = yz;
        sm[3 * MM + m] = 0.5f * fmaf(yz, yz, fmaf(yy, yy, yx * yx));
    }

    const int lane = threadIdx.x & 31;
    const int warp = threadIdx.x >> 5;
    const int q    = lane >> 3;        // 4 interleaved M-slices
    const int sub  = lane & 7;
    const int n0   = blockIdx.x * 128 + warp * 32 + sub * 4;  // 4 points/thread

    // Refined state lives in registers across iterations.
    float x0[4], x1[4], x2[4];
    {
        const float* rp = pred + ((size_t)b * NN + n0) * 3;
#pragma unroll
        for (int i = 0; i < 4; i++) {
            x0[i] = rp[i * 3 + 0];
            x1[i] = rp[i * 3 + 1];
            x2[i] = rp[i * 3 + 2];
        }
    }
    __syncthreads();

    for (int it = 0; it < NUM_ITER; it++) {
        uint64_t xp0[4], xp1[4], xp2[4];
        float xs[4];
#pragma unroll
        for (int i = 0; i < 4; i++) {
            xp0[i] = pack2(-x0[i], -x0[i]);
            xp1[i] = pack2(-x1[i], -x1[i]);
            xp2[i] = pack2(-x2[i], -x2[i]);
            xs[i]  = fmaf(x2[i], x2[i], fmaf(x1[i], x1[i], x0[i] * x0[i]));
        }

        // Per point: best 8-m group-min value + group index (64 groups).
        float best[4] = {3.4e38f, 3.4e38f, 3.4e38f, 3.4e38f};
        int   bg[4]   = {0, 0, 0, 0};

        // Slice q's vectors: v = 4k + q. Segment of 16 k-steps = 64 vectors.
        const ulonglong2* pv = reinterpret_cast<const ulonglong2*>(sm) + q;

#pragma unroll 1
        for (int outer = 0; outer < 8; outer++) {
            const int gb = outer * 8;          // group base for this segment
            const ulonglong2* pvb = pv + outer * 64;
#pragma unroll
            for (int kk = 0; kk < 16; kk += 2) {
                // quad-min of k-step kk and kk+1, per point
                float qm0[4], qm1[4];
                {
                    const ulonglong2* vb = pvb + 4 * kk;
                    ulonglong2 vx = vb[0];
                    ulonglong2 vy = vb[MM / 4];       // +MM floats
                    ulonglong2 vz = vb[2 * (MM / 4)];
                    ulonglong2 vh = vb[3 * (MM / 4)];
#pragma unroll
                    for (int i = 0; i < 4; i++) {
                        uint64_t t01 = ffma2(xp0[i], vx.x, vh.x);
                        t01 = ffma2(xp1[i], vy.x, t01);
                        t01 = ffma2(xp2[i], vz.x, t01);
                        uint64_t t23 = ffma2(xp0[i], vx.y, vh.y);
                        t23 = ffma2(xp1[i], vy.y, t23);
                        t23 = ffma2(xp2[i], vz.y, t23);
                        float t0, t1, t2, t3;
                        unpack2(t01, t0, t1);
                        unpack2(t23, t2, t3);
                        qm0[i] = fminf(fminf(t0, t1), fminf(t2, t3));
                    }
                }
                {
                    const ulonglong2* vb = pvb + 4 * (kk + 1);
                    ulonglong2 vx = vb[0];
                    ulonglong2 vy = vb[MM / 4];
                    ulonglong2 vz = vb[2 * (MM / 4)];
                    ulonglong2 vh = vb[3 * (MM / 4)];
#pragma unroll
                    for (int i = 0; i < 4; i++) {
                        uint64_t t01 = ffma2(xp0[i], vx.x, vh.x);
                        t01 = ffma2(xp1[i], vy.x, t01);
                        t01 = ffma2(xp2[i], vz.x, t01);
                        uint64_t t23 = ffma2(xp0[i], vx.y, vh.y);
                        t23 = ffma2(xp1[i], vy.y, t23);
                        t23 = ffma2(xp2[i], vz.y, t23);
                        float t0, t1, t2, t3;
                        unpack2(t01, t0, t1);
                        unpack2(t23, t2, t3);
                        qm1[i] = fminf(fminf(t0, t1), fminf(t2, t3));
                    }
                }
                const int g = gb + (kk >> 1);
#pragma unroll
                for (int i = 0; i < 4; i++) {
                    float gm = fminf(qm0[i], qm1[i]);
                    bool c = gm < best[i];   // strict: earliest group kept
                    best[i] = c ? gm : best[i];
                    bg[i]   = c ? g  : bg[i];
                }
            }
        }

        // Recover exact m inside each point's winning 16-candidate group
        // (two vectors: k=2g and k=2g+1 of slice q). Bit-exact scalar
        // recompute; scan m DESCENDING so smallest matching m survives.
        float bv[4];
        int   bm[4];
#pragma unroll
        for (int i = 0; i < 4; i++) {
            const int g = bg[i];
            const int mA = (8 * g + q) * 4;      // first m of vector k=2g
            const int mB = (8 * g + 4 + q) * 4;  // first m of vector k=2g+1
            int bmi = mA;  // overwritten by the guaranteed match below
#pragma unroll
            for (int idx = 7; idx >= 0; idx--) {
                int mj = (idx >= 4) ? (mB + (idx - 4)) : (mA + idx);
                float tj = fmaf(-x2[i], sm[2 * MM + mj],
                           fmaf(-x1[i], sm[MM + mj],
                           fmaf(-x0[i], sm[mj], sm[3 * MM + mj])));
                if (tj == best[i]) bmi = mj;
            }
            bv[i] = best[i];
            bm[i] = bmi;
        }

        // Butterfly merge across the 4 slices (bits 3,4): all lanes end with
        // the merged (value, m) for their 4 points. Tie -> smaller m.
#pragma unroll
        for (int r = 8; r <= 16; r <<= 1) {
#pragma unroll
            for (int i = 0; i < 4; i++) {
                float ob = __shfl_xor_sync(0xffffffffu, bv[i], r);
                int   oi = __shfl_xor_sync(0xffffffffu, bm[i], r);
                if (ob < bv[i] || (ob == bv[i] && oi < bm[i])) { bv[i] = ob; bm[i] = oi; }
            }
        }

        // min_dist per point (identical across q-lanes).
        float md[4];
        float mloc = 0.0f;
#pragma unroll
        for (int i = 0; i < 4; i++) {
            float d2 = fmaf(2.0f, bv[i], xs[i]);
            md[i] = sqrtf(fmaxf(d2, 0.0f));
            mloc = fmaxf(mloc, md[i]);
        }

        // Block max -> one atomicMax per block (md >= 0: int order == float).
#pragma unroll
        for (int o = 16; o > 0; o >>= 1)
            mloc = fmaxf(mloc, __shfl_xor_sync(0xffffffffu, mloc, o));
        if (lane == 0) smax[warp] = mloc;
        __syncthreads();

        const int slot = it * BB + b;
        if (threadIdx.x == 0) {
            float m01 = fmaxf(smax[0], smax[1]);
            float m23 = fmaxf(smax[2], smax[3]);
            atomicMax(&g_maxbits[slot], __float_as_int(fmaxf(m01, m23)));
            __threadfence();  // publish max before arrival
            atomicAdd(&g_arrive[slot], 1);
            while (*(volatile int*)&g_arrive[slot] < BLOCKS_PER_BATCH) { }
            __threadfence();
            s_mx = __int_as_float(__ldcg(&g_maxbits[slot]));
        }
        __syncthreads();
        const float mxp = s_mx + 1e-6f;

        // Register-local blend update (all lanes, same result per point).
#pragma unroll
        for (int i = 0; i < 4; i++) {
            int mi = bm[i];
            float alpha = BASE_ALPHA * (2.0f - md[i] / mxp);
            x0[i] = fmaf(alpha, sm[mi]          - x0[i], x0[i]);
            x1[i] = fmaf(alpha, sm[MM + mi]     - x1[i], x1[i]);
            x2[i] = fmaf(alpha, sm[2 * MM + mi] - x2[i], x2[i]);
        }
    }

    // Final store (q==0 lanes own the write; values identical across q).
    if (q == 0) {
        float* rp = out + ((size_t)b * NN + n0) * 3;
#pragma unroll
        for (int i = 0; i < 4; i++) {
            rp[i * 3 + 0] = x0[i];
            rp[i * 3 + 1] = x1[i];
            rp[i * 3 + 2] = x2[i];
        }
    }
}

// ---------------------------------------------------------------------------
extern "C" void kernel_launch(void* const* d_in, const int* in_sizes, int n_in,
                              void* d_out, int out_size) {
    const float* pred    = (const float*)d_in[0];  // [8, 8192, 3] f32
    const float* partial = (const float*)d_in[1];  // [8, 2048, 3] f32
    float* out = (float*)d_out;                     // [8, 8192, 3] f32

    (void)in_sizes; (void)n_in; (void)out_size;

    ipgr_init_kernel<<<1, 64>>>();

    dim3 grid(NN / 128, BB);  // (64, 8) = 512 blocks, all co-resident
    ipgr_persist_kernel<<<grid, 128>>>(pred, partial, out);
}